// round 1
// baseline (speedup 1.0000x reference)
#include <cuda_runtime.h>
#include <cstdint>

#define N 2048
#define D 1024
#define C 10
#define CP 12           // padded class dim (exp pads = 0 -> dot over 12 == dot over 10)
#define GCE_Q 0.7f
#define EPS 1e-8f

// -------- device scratch (no allocations allowed) --------
// i-side (rows of z_c)
__device__ float g_iEAc[N * CP];  // exp(Ac'[i,c] - mAc[i]), pad 0
__device__ float g_iEAb[N * CP];  // exp(Ab'[i,c] - mAb[i]), pad 0
__device__ float g_iAbp[N * CP];  // raw Ab'[i,c] (= z_c@Wb.T + bb), pad 0
__device__ float g_imAc[N], g_imAb[N];
__device__ float g_iacy[N];       // Ac'[i, y[i]]
__device__ float g_iaby[N];       // Ab'[i, y[i]]
// j-side (rows of z_b)
__device__ float g_jEBc[N * CP];  // exp(Bc[j,c] - mBc[j]), pad 0
__device__ float g_jEBb[N * CP];
__device__ float g_jBc[N * CP];   // raw Bc[j,c]
__device__ float g_jBb[N * CP];   // raw Bb[j,c]
__device__ float g_jmBc[N], g_jmBb[N];
__device__ float g_jbby[N];       // Bb[j, y[j]]

// ============================================================
// Kernel 1: per-row projections + softmax stats.
// grid = (2048, 2): blockIdx.y==0 -> z_c row (A side, add bias)
//                   blockIdx.y==1 -> z_b row (B side, no bias)
// block = 128 threads
// ============================================================
__global__ void __launch_bounds__(128) rowstats_kernel(
    const float* __restrict__ zc, const float* __restrict__ zb,
    const float* __restrict__ Wc, const float* __restrict__ bc,
    const float* __restrict__ Wb, const float* __restrict__ bb,
    const int* __restrict__ y)
{
    const int row  = blockIdx.x;
    const int side = blockIdx.y;   // 0: A side (z_c), 1: B side (z_b)
    const float* z = (side == 0 ? zc : zb) + (size_t)row * D;

    const int t = threadIdx.x;

    float accC[10], accB[10];
#pragma unroll
    for (int c = 0; c < 10; c++) { accC[c] = 0.f; accB[c] = 0.f; }

    const float4* z4 = (const float4*)z;
#pragma unroll
    for (int k = 0; k < 2; k++) {
        const int d4 = t + k * 128;          // 256 float4 per row
        const float4 zv = z4[d4];
#pragma unroll
        for (int c = 0; c < 10; c++) {
            const float4 wc = ((const float4*)(Wc + c * D))[d4];
            accC[c] += zv.x * wc.x + zv.y * wc.y + zv.z * wc.z + zv.w * wc.w;
            const float4 wb = ((const float4*)(Wb + c * D))[d4];
            accB[c] += zv.x * wb.x + zv.y * wb.y + zv.z * wb.z + zv.w * wb.w;
        }
    }

    // warp shuffle reduce
#pragma unroll
    for (int off = 16; off > 0; off >>= 1) {
#pragma unroll
        for (int c = 0; c < 10; c++) {
            accC[c] += __shfl_down_sync(0xffffffffu, accC[c], off);
            accB[c] += __shfl_down_sync(0xffffffffu, accB[c], off);
        }
    }

    __shared__ float red[4][20];
    __shared__ float vals[20];
    const int warp = t >> 5, lane = t & 31;
    if (lane == 0) {
#pragma unroll
        for (int c = 0; c < 10; c++) {
            red[warp][c]      = accC[c];
            red[warp][10 + c] = accB[c];
        }
    }
    __syncthreads();

    if (t < 20) {
        float v = red[0][t] + red[1][t] + red[2][t] + red[3][t];
        if (side == 0) v += (t < 10) ? bc[t] : bb[t - 10];  // bias folded into A side
        vals[t] = v;
    }
    __syncthreads();

    if (t < 20) {
        const int head = t / 10, c = t % 10;
        float m = vals[head * 10];
#pragma unroll
        for (int k = 1; k < 10; k++) m = fmaxf(m, vals[head * 10 + k]);
        const float v = vals[t];
        const float e = __expf(v - m);
        const size_t o = (size_t)row * CP + c;
        if (side == 0) {
            if (head == 0) {
                g_iEAc[o] = e;
                if (c == 0) g_imAc[row] = m;
            } else {
                g_iEAb[o] = e;
                g_iAbp[o] = v;
                if (c == 0) g_imAb[row] = m;
            }
        } else {
            if (head == 0) {
                g_jEBc[o] = e;
                g_jBc[o] = v;
                if (c == 0) g_jmBc[row] = m;
            } else {
                g_jEBb[o] = e;
                g_jBb[o] = v;
                if (c == 0) g_jmBb[row] = m;
            }
        }
    }
    if (t == 20) {   // zero the pad lanes (10, 11)
        const size_t o = (size_t)row * CP;
        if (side == 0) {
            g_iEAc[o + 10] = 0.f; g_iEAc[o + 11] = 0.f;
            g_iEAb[o + 10] = 0.f; g_iEAb[o + 11] = 0.f;
            g_iAbp[o + 10] = 0.f; g_iAbp[o + 11] = 0.f;
        } else {
            g_jEBc[o + 10] = 0.f; g_jEBc[o + 11] = 0.f;
            g_jEBb[o + 10] = 0.f; g_jEBb[o + 11] = 0.f;
            g_jBc[o + 10]  = 0.f; g_jBc[o + 11]  = 0.f;
            g_jBb[o + 10]  = 0.f; g_jBb[o + 11]  = 0.f;
        }
    }
    if (t == 21) {
        const int yr = y[row];
        if (side == 0) {
            g_iacy[row] = vals[yr];
            g_iaby[row] = vals[10 + yr];
        } else {
            g_jbby[row] = vals[10 + yr];
        }
    }
}

// ============================================================
// Kernel 2: 64x64 output tile per block, 256 threads, 4x4 per thread.
// grid = (32, 32): blockIdx.x -> j tile, blockIdx.y -> i tile
// ============================================================
__global__ void __launch_bounds__(256) pair_kernel(
    const int* __restrict__ y, float* __restrict__ out)
{
    __shared__ float sEAc[64 * CP], sEAb[64 * CP], sAbp[64 * CP];
    __shared__ float sEBc[64 * CP], sEBb[64 * CP], sBc[64 * CP], sBb[64 * CP];
    __shared__ float smAc[64], smAb[64], sacy[64], saby[64];
    __shared__ float smBc[64], smBb[64], sbby[64];
    __shared__ int   syi[64], syj[64];

    const int i0 = blockIdx.y * 64;
    const int j0 = blockIdx.x * 64;
    const int tid = threadIdx.x;

    // stage padded [64][12] arrays via float4 (768 floats = 192 float4 each)
    if (tid < 192) {
        const size_t io = (size_t)i0 * CP / 4;
        const size_t jo = (size_t)j0 * CP / 4;
        ((float4*)sEAc)[tid] = ((const float4*)g_iEAc)[io + tid];
        ((float4*)sEAb)[tid] = ((const float4*)g_iEAb)[io + tid];
        ((float4*)sAbp)[tid] = ((const float4*)g_iAbp)[io + tid];
        ((float4*)sEBc)[tid] = ((const float4*)g_jEBc)[jo + tid];
        ((float4*)sEBb)[tid] = ((const float4*)g_jEBb)[jo + tid];
        ((float4*)sBc)[tid]  = ((const float4*)g_jBc)[jo + tid];
        ((float4*)sBb)[tid]  = ((const float4*)g_jBb)[jo + tid];
    }
    if (tid < 64) {
        smAc[tid] = g_imAc[i0 + tid];
        smAb[tid] = g_imAb[i0 + tid];
        sacy[tid] = g_iacy[i0 + tid];
        saby[tid] = g_iaby[i0 + tid];
        syi[tid]  = y[i0 + tid];
    } else if (tid < 128) {
        const int u = tid - 64;
        smBc[u] = g_jmBc[j0 + u];
        smBb[u] = g_jmBb[j0 + u];
        sbby[u] = g_jbby[j0 + u];
        syj[u]  = y[j0 + u];
    }
    __syncthreads();

    const int tx = tid & 15;        // j group
    const int ty = tid >> 4;        // i group
    const int il = ty * 4;
    const int jl = tx * 4;

    float Sc[4][4], Sb[4][4];
#pragma unroll
    for (int a = 0; a < 4; a++)
#pragma unroll
        for (int b = 0; b < 4; b++) { Sc[a][b] = 0.f; Sb[a][b] = 0.f; }

    // rank-12 (rank-10 + zero pad) dot products, outer-product style
#pragma unroll
    for (int cg = 0; cg < 3; cg++) {
        float4 eac[4], eab[4], ebc[4], ebb[4];
#pragma unroll
        for (int a = 0; a < 4; a++) {
            eac[a] = *(const float4*)&sEAc[(il + a) * CP + cg * 4];
            eab[a] = *(const float4*)&sEAb[(il + a) * CP + cg * 4];
        }
#pragma unroll
        for (int b = 0; b < 4; b++) {
            ebc[b] = *(const float4*)&sEBc[(jl + b) * CP + cg * 4];
            ebb[b] = *(const float4*)&sEBb[(jl + b) * CP + cg * 4];
        }
#pragma unroll
        for (int a = 0; a < 4; a++) {
#pragma unroll
            for (int b = 0; b < 4; b++) {
                Sc[a][b] += eac[a].x * ebc[b].x + eac[a].y * ebc[b].y
                          + eac[a].z * ebc[b].z + eac[a].w * ebc[b].w;
                Sb[a][b] += eab[a].x * ebb[b].x + eab[a].y * ebb[b].y
                          + eab[a].z * ebb[b].z + eab[a].w * ebb[b].w;
            }
        }
    }

    // hoist per-i / per-j scalars
    float mAc_i[4], mAb_i[4], acy_i[4], aby_i[4];
    int   yi_i[4];
    float mBc_j[4], mBb_j[4], bby_j[4];
    int   yj_j[4];
#pragma unroll
    for (int a = 0; a < 4; a++) {
        mAc_i[a] = smAc[il + a];
        mAb_i[a] = smAb[il + a];
        acy_i[a] = sacy[il + a];
        aby_i[a] = saby[il + a];
        yi_i[a]  = syi[il + a];
    }
#pragma unroll
    for (int b = 0; b < 4; b++) {
        mBc_j[b] = smBc[jl + b];
        mBb_j[b] = smBb[jl + b];
        bby_j[b] = sbby[jl + b];
        yj_j[b]  = syj[jl + b];
    }

#pragma unroll
    for (int a = 0; a < 4; a++) {
        float r[4];
#pragma unroll
        for (int b = 0; b < 4; b++) {
            const int yi = yi_i[a];
            const float lse_c = mAc_i[a] + mBc_j[b] + __logf(Sc[a][b]);
            const float ce_pc = lse_c - acy_i[a] - sBc[(jl + b) * CP + yi];

            const float lse_b = mAb_i[a] + mBb_j[b] + __logf(Sb[a][b]);
            const float ce_pb = lse_b - aby_i[a] - sBb[(jl + b) * CP + yi];

            const float logp = sAbp[(il + a) * CP + yj_j[b]] + bby_j[b] - lse_b;
            const float gce  = -logp * __expf(GCE_Q * logp);

            const float w = __fdividef(ce_pb, ce_pc + ce_pb + EPS);
            r[b] = w * ce_pc + (1.0f - w) * gce;
        }
        float4 v; v.x = r[0]; v.y = r[1]; v.z = r[2]; v.w = r[3];
        *(float4*)&out[(size_t)(i0 + il + a) * N + (j0 + jl)] = v;
    }
}

// ============================================================
extern "C" void kernel_launch(void* const* d_in, const int* in_sizes, int n_in,
                              void* d_out, int out_size)
{
    const float* zc = (const float*)d_in[0];  // [N, D]
    const float* zb = (const float*)d_in[1];  // [N, D]
    const float* Wc = (const float*)d_in[2];  // [C, D]
    const float* bc = (const float*)d_in[3];  // [C]
    const float* Wb = (const float*)d_in[4];  // [C, D]
    const float* bb = (const float*)d_in[5];  // [C]
    const int*   y  = (const int*)d_in[6];    // [N]
    float* out = (float*)d_out;               // [N, N]

    dim3 g1(N, 2);
    rowstats_kernel<<<g1, 128>>>(zc, zb, Wc, bc, Wb, bb, y);

    dim3 g2(N / 64, N / 64);
    pair_kernel<<<g2, 256>>>(y, out);
}

// round 3
// speedup vs baseline: 1.6323x; 1.6323x over previous
#include <cuda_runtime.h>
#include <cstdint>

#define N 2048
#define D 1024
#define GCE_Q 0.7f
#define EPS 1e-8f

#define CP2 28   // interleaved exp row stride (words): 14 class slots x 2 heads; stride%32=28 -> conflict-free LDS.128
#define CPS 13   // scalar raw row stride (odd -> conflict-free scalar LDS)

// -------- device scratch (no allocations) --------
__device__ __align__(16) float g_iEA2[N * CP2];  // i-side interleaved: [row][c][head] = exp(val - m); pads 0
__device__ __align__(16) float g_jEB2[N * CP2];  // j-side interleaved
__device__ float g_iAbpM[N * CPS];   // Ab'[i,c] - mAb[i]
__device__ float g_jBcM[N * CPS];    // mBc[j] - Bc[j,c]
__device__ float g_jBbM[N * CPS];    // mBb[j] - Bb[j,c]
__device__ float g_iacyM[N];         // Ac'[i,y[i]] - mAc[i]
__device__ float g_iabyM[N];         // Ab'[i,y[i]] - mAb[i]
__device__ float g_jbbyM[N];         // Bb[j,y[j]] - mBb[j]

// ============================================================
// Kernel 1: 8 rows per block, 128 threads. W loads amortized over
// 8 rows; smem-matrix cross-thread reduction (stride 85, odd ->
// conflict-free). Virtual rows [0,2048)=z_c side, [2048,4096)=z_b.
// ============================================================
#define K1_ROWS 8
#define K1_THR 128
#define RSTR 85

__global__ void __launch_bounds__(K1_THR) rowstats_kernel(
    const float* __restrict__ zc, const float* __restrict__ zb,
    const float* __restrict__ Wc, const float* __restrict__ bc,
    const float* __restrict__ Wb, const float* __restrict__ bb,
    const int* __restrict__ y)
{
    __shared__ float red[K1_THR * RSTR];     // 43.5 KB partials
    __shared__ float vals[K1_ROWS * 20];     // reduced logits [row][head*10+c]

    const int t = threadIdx.x;
    const int vr0 = blockIdx.x * K1_ROWS;
    const int side = vr0 >> 11;              // 0 -> z_c (A side), 1 -> z_b (B side)
    const int grow0 = vr0 & (N - 1);

    const float4* z4 = (const float4*)((side ? zb : zc) + (size_t)grow0 * D);

    for (int h = 0; h < 2; h++) {
        const float4* w4 = (const float4*)(h ? Wb : Wc);
        float acc[K1_ROWS][10];
#pragma unroll
        for (int r = 0; r < K1_ROWS; r++)
#pragma unroll
            for (int c = 0; c < 10; c++) acc[r][c] = 0.f;

#pragma unroll
        for (int kk = 0; kk < 2; kk++) {
            const int d4 = t + kk * K1_THR;   // 256 float4 per row
            float4 zv[K1_ROWS];
#pragma unroll
            for (int r = 0; r < K1_ROWS; r++) zv[r] = z4[r * 256 + d4];
#pragma unroll
            for (int c = 0; c < 10; c++) {
                const float4 wv = w4[c * 256 + d4];
#pragma unroll
                for (int r = 0; r < K1_ROWS; r++) {
                    acc[r][c] = fmaf(zv[r].x, wv.x,
                                fmaf(zv[r].y, wv.y,
                                fmaf(zv[r].z, wv.z,
                                fmaf(zv[r].w, wv.w, acc[r][c]))));
                }
            }
        }

        // dump partials to smem
#pragma unroll
        for (int r = 0; r < K1_ROWS; r++)
#pragma unroll
            for (int c = 0; c < 10; c++)
                red[t * RSTR + r * 10 + c] = acc[r][c];
        __syncthreads();

        if (t < 80) {
            const int c = t % 10;
            float s0 = 0.f, s1 = 0.f, s2 = 0.f, s3 = 0.f;
#pragma unroll 8
            for (int u = 0; u < K1_THR; u += 4) {
                s0 += red[(u + 0) * RSTR + t];
                s1 += red[(u + 1) * RSTR + t];
                s2 += red[(u + 2) * RSTR + t];
                s3 += red[(u + 3) * RSTR + t];
            }
            float s = (s0 + s1) + (s2 + s3);
            if (side == 0) s += (h ? bb[c] : bc[c]);   // bias folded into A side
            vals[(t / 10) * 20 + h * 10 + c] = s;
        }
        __syncthreads();
    }

    // per-row softmax stats -> globals (pre-folded forms)
    for (int v = t; v < K1_ROWS * 20; v += K1_THR) {
        const int row = v / 20, idx = v % 20, h = idx / 10, c = idx % 10;
        const int grow = grow0 + row;
        const float* vrow = &vals[row * 20 + h * 10];
        float m = vrow[0];
#pragma unroll
        for (int k = 1; k < 10; k++) m = fmaxf(m, vrow[k]);
        const float val = vrow[c];
        const float e = __expf(val - m);
        if (side == 0) {
            if (h == 0) {
                g_iEA2[grow * CP2 + 2 * c] = e;
                if (c == 0) g_iacyM[grow] = vrow[y[grow]] - m;
            } else {
                g_iEA2[grow * CP2 + 2 * c + 1] = e;
                g_iAbpM[grow * CPS + c] = val - m;
                if (c == 0) g_iabyM[grow] = vrow[y[grow]] - m;
            }
        } else {
            if (h == 0) {
                g_jEB2[grow * CP2 + 2 * c] = e;
                g_jBcM[grow * CPS + c] = m - val;
            } else {
                g_jEB2[grow * CP2 + 2 * c + 1] = e;
                g_jBbM[grow * CPS + c] = m - val;
                if (c == 0) g_jbbyM[grow] = vrow[y[grow]] - m;
            }
        }
    }
    // zero the pad class slots (words 20..27) of interleaved exp rows
    for (int p = t; p < K1_ROWS * 8; p += K1_THR) {
        const int row = p / 8, w = p % 8;
        const int grow = grow0 + row;
        if (side == 0) g_iEA2[grow * CP2 + 20 + w] = 0.f;
        else           g_jEB2[grow * CP2 + 20 + w] = 0.f;
    }
}

// ============================================================
// Kernel 2: 64x64 tile / block, 256 threads, 4x4 per thread.
// j rows per thread = {tx, tx+16, tx+32, tx+48}: lane stride = 1 row
// -> conflict-free smem (row stride 28 words). Both heads' dots via
// packed fma.rn.f32x2 (lo = causal, hi = bias).
// ============================================================
__device__ __forceinline__ void fma2(unsigned long long& acc,
                                     unsigned long long a, unsigned long long b) {
    asm("fma.rn.f32x2 %0, %1, %2, %0;" : "+l"(acc) : "l"(a), "l"(b));
}
__device__ __forceinline__ float f2lo(unsigned long long v) {
    return __uint_as_float((unsigned)(v & 0xffffffffull));
}
__device__ __forceinline__ float f2hi(unsigned long long v) {
    return __uint_as_float((unsigned)(v >> 32));
}

__global__ void __launch_bounds__(256) pair_kernel(
    const int* __restrict__ y, float* __restrict__ out)
{
    __shared__ __align__(16) float sEA2[64 * CP2];
    __shared__ __align__(16) float sEB2[64 * CP2];
    __shared__ float sAbpM[64 * CPS];
    __shared__ float sBcM[64 * CPS];
    __shared__ float sBbM[64 * CPS];
    __shared__ float sacyM[64], sabyM[64], sbbyM[64];
    __shared__ int   syi[64], syj[64];

    const int i0 = blockIdx.y * 64;
    const int j0 = blockIdx.x * 64;
    const int tid = threadIdx.x;

    // stage interleaved exp tables (7 float4 per row)
    for (int idx = tid; idx < 64 * (CP2 / 4); idx += 256) {
        ((float4*)sEA2)[idx] = ((const float4*)g_iEA2)[i0 * (CP2 / 4) + idx];
        ((float4*)sEB2)[idx] = ((const float4*)g_jEB2)[j0 * (CP2 / 4) + idx];
    }
    // stage scalar tables (stride 13)
    for (int idx = tid; idx < 64 * CPS; idx += 256) {
        sAbpM[idx] = g_iAbpM[i0 * CPS + idx];
        sBcM[idx]  = g_jBcM[j0 * CPS + idx];
        sBbM[idx]  = g_jBbM[j0 * CPS + idx];
    }
    if (tid < 64) {
        sacyM[tid] = g_iacyM[i0 + tid];
        sabyM[tid] = g_iabyM[i0 + tid];
        syi[tid]   = y[i0 + tid];
    } else if (tid < 128) {
        const int u = tid - 64;
        sbbyM[u] = g_jbbyM[j0 + u];
        syj[u]   = y[j0 + u];
    }
    __syncthreads();

    const int tx = tid & 15;
    const int ty = tid >> 4;
    const int il = ty * 4;

    unsigned long long acc[4][4];
#pragma unroll
    for (int a = 0; a < 4; a++)
#pragma unroll
        for (int b = 0; b < 4; b++) acc[a][b] = 0ull;

    // rank-12 dot (classes 0..11; 10,11 zero pads), both heads packed
#pragma unroll
    for (int g = 0; g < 6; g++) {
        ulonglong2 ea[4], eb[4];
#pragma unroll
        for (int a = 0; a < 4; a++)
            ea[a] = *(const ulonglong2*)&sEA2[(il + a) * CP2 + g * 4];
#pragma unroll
        for (int b = 0; b < 4; b++)
            eb[b] = *(const ulonglong2*)&sEB2[(tx + 16 * b) * CP2 + g * 4];
#pragma unroll
        for (int a = 0; a < 4; a++)
#pragma unroll
            for (int b = 0; b < 4; b++) {
                fma2(acc[a][b], ea[a].x, eb[b].x);
                fma2(acc[a][b], ea[a].y, eb[b].y);
            }
    }

    float acy[4], aby[4];
    int   yia[4];
#pragma unroll
    for (int a = 0; a < 4; a++) {
        acy[a] = sacyM[il + a];
        aby[a] = sabyM[il + a];
        yia[a] = syi[il + a];
    }
    float bby[4];
    int   yjb[4], jr[4];
#pragma unroll
    for (int b = 0; b < 4; b++) {
        jr[b]  = tx + 16 * b;
        bby[b] = sbbyM[jr[b]];
        yjb[b] = syj[jr[b]];
    }

#pragma unroll
    for (int a = 0; a < 4; a++) {
        float* orow = out + (size_t)(i0 + il + a) * N + j0;
#pragma unroll
        for (int b = 0; b < 4; b++) {
            const float Sc = f2lo(acc[a][b]);
            const float Sb = f2hi(acc[a][b]);
            const float lc = __logf(Sc);
            const float lb = __logf(Sb);
            const float ce_pc = lc - acy[a] + sBcM[jr[b] * CPS + yia[a]];
            const float ce_pb = lb - aby[a] + sBbM[jr[b] * CPS + yia[a]];
            const float logp  = sAbpM[(il + a) * CPS + yjb[b]] + bby[b] - lb;
            const float gce   = -logp * __expf(GCE_Q * logp);
            const float w = __fdividef(ce_pb, ce_pc + ce_pb + EPS);
            orow[jr[b]] = fmaf(w, ce_pc - gce, gce);
        }
    }
}

// ============================================================
extern "C" void kernel_launch(void* const* d_in, const int* in_sizes, int n_in,
                              void* d_out, int out_size)
{
    const float* zc = (const float*)d_in[0];  // [N, D]
    const float* zb = (const float*)d_in[1];  // [N, D]
    const float* Wc = (const float*)d_in[2];  // [C, D]
    const float* bc = (const float*)d_in[3];  // [C]
    const float* Wb = (const float*)d_in[4];  // [C, D]
    const float* bb = (const float*)d_in[5];  // [C]
    const int*   y  = (const int*)d_in[6];    // [N]
    float* out = (float*)d_out;               // [N, N]

    rowstats_kernel<<<(2 * N) / K1_ROWS, K1_THR>>>(zc, zb, Wc, bc, Wb, bb, y);

    dim3 g2(N / 64, N / 64);
    pair_kernel<<<g2, 256>>>(y, out);
}